// round 16
// baseline (speedup 1.0000x reference)
#include <cuda_runtime.h>
#include <cstdint>

#define LQ 4096
#define BB 8
#define DM 1024
#define NH 16
#define DH 64
#define NS 128

// ---------------------------------------------------------------------------
// Scratch (static device globals — allocation-free per harness rules)
// k-dim of all GEMM operands is stored PERMUTED within 8-blocks:
//   pos(k) = (k & ~7) | ((k&3)<<1) | ((k&4)>>2)
// so that mma's per-thread k-pair (k, k+4) is memory-adjacent (LDS.64 frags).
// q is NOT pre-passed anymore: the q-proj GEMM loader rounds+permutes inline.
// ---------------------------------------------------------------------------
__device__ float g_qp[(size_t)BB * NH * LQ * DH];   // [b][h][i][dh]   (tf32, unpermuted)
__device__ float g_kp[BB * NH * NS * DH];           // [b][h][s][dh]   (tf32, unpermuted)
__device__ float g_vpT[BB * NH * DH * NS];          // [b][h][d][s]    (tf32, unpermuted)
__device__ float g_ctx[(size_t)LQ * BB * DM];       // [i*B+b][D]      (tf32, k-PERMUTED)
__device__ float g_kg[NS * BB * DM];                // gathered k rows (k-PERMUTED)
__device__ float g_vg[NS * BB * DM];                // gathered v rows (k-PERMUTED)
__device__ float g_wr[3 * DM * DM];                 // in_proj_weight  (k-PERMUTED)
__device__ float g_owr[DM * DM];                    // out_w           (k-PERMUTED)
__device__ int   g_sidx[NS];
__device__ int   g_mkl[BB];

__device__ __forceinline__ uint32_t smem_u32(const void* p) {
    return (uint32_t)__cvta_generic_to_shared(p);
}
__device__ __forceinline__ float tf32r(float x) {   // round-to-nearest tf32
    uint32_t u;
    asm volatile("cvt.rna.tf32.f32 %0, %1;\n" : "=r"(u) : "f"(x));
    return __uint_as_float(u);
}
__device__ __forceinline__ int kperm(int k) {       // within-8 interleave
    return (k & ~7) | ((k & 3) << 1) | ((k & 4) >> 2);
}
__device__ __forceinline__ void mma_tf32(float4& d, const uint32_t a[4], const uint32_t b[2]) {
    asm volatile(
        "mma.sync.aligned.m16n8k8.row.col.f32.tf32.tf32.f32 "
        "{%0,%1,%2,%3}, {%4,%5,%6,%7}, {%8,%9}, {%0,%1,%2,%3};\n"
        : "+f"(d.x), "+f"(d.y), "+f"(d.z), "+f"(d.w)
        : "r"(a[0]), "r"(a[1]), "r"(a[2]), "r"(a[3]), "r"(b[0]), "r"(b[1]));
}

// ---------------------------------------------------------------------------
// Setup: normalize sampled_index / key_length (int32 or int64 on the wire).
// ---------------------------------------------------------------------------
__global__ void setup_kernel(const void* sidx_raw, const void* klen_raw)
{
    __shared__ int s_sidx[NS];
    __shared__ int s_klen[BB];
    int t = threadIdx.x;  // 128 threads

    const int* si = (const int*)sidx_raw;
    int sv;
    if (si[1] == 0) sv = (int)((const long long*)sidx_raw)[t];
    else            sv = si[t];
    s_sidx[t] = sv;
    g_sidx[t] = sv;

    if (t < BB) {
        const int* ki = (const int*)klen_raw;
        int kv;
        if (ki[1] == 0) kv = (int)((const long long*)klen_raw)[t];
        else            kv = ki[t];
        s_klen[t] = kv;
    }
    __syncthreads();
    if (t < BB) {
        int c = 0;
        for (int s = 0; s < NS; s++) c += (s_sidx[s] < s_klen[t]) ? 1 : 0;
        g_mkl[t] = c;
    }
}

// ---------------------------------------------------------------------------
// Pre-round fp32 -> tf32 AND apply the within-8 k-permutation (weights only).
// sel: 1=g_wr 2=g_owr
// ---------------------------------------------------------------------------
__global__ void round_perm_kernel(const float4* __restrict__ src, int n8, int sel)
{
    float4* dst = sel == 1 ? (float4*)g_wr : (float4*)g_owr;
    for (int i = blockIdx.x * blockDim.x + threadIdx.x; i < n8; i += gridDim.x * blockDim.x) {
        float4 a = src[2 * i];
        float4 b = src[2 * i + 1];
        float4 o0, o1;
        o0.x = tf32r(a.x); o0.y = tf32r(b.x); o0.z = tf32r(a.y); o0.w = tf32r(b.y);
        o1.x = tf32r(a.z); o1.y = tf32r(b.z); o1.z = tf32r(a.w); o1.w = tf32r(b.w);
        dst[2 * i] = o0;
        dst[2 * i + 1] = o1;
    }
}

// Gather sampled k/v rows, round + permute: row = s*BB+b -> src row sidx[s]*BB+b
__global__ void gather_round_kernel(const float* __restrict__ k, const float* __restrict__ v)
{
    int row = blockIdx.x;                      // 0..1023
    int src = g_sidx[row >> 3] * BB + (row & 7);
    const float4* ks = (const float4*)(k + (size_t)src * DM);
    const float4* vs = (const float4*)(v + (size_t)src * DM);
    float4* kd = (float4*)(g_kg + (size_t)row * DM);
    float4* vd = (float4*)(g_vg + (size_t)row * DM);
    int t = threadIdx.x;                       // 128 threads, DM/8 = 128 blocks
    {
        float4 a = ks[2 * t], b = ks[2 * t + 1];
        float4 o0, o1;
        o0.x = tf32r(a.x); o0.y = tf32r(b.x); o0.z = tf32r(a.y); o0.w = tf32r(b.y);
        o1.x = tf32r(a.z); o1.y = tf32r(b.z); o1.z = tf32r(a.w); o1.w = tf32r(b.w);
        kd[2 * t] = o0; kd[2 * t + 1] = o1;
    }
    {
        float4 a = vs[2 * t], b = vs[2 * t + 1];
        float4 o0, o1;
        o0.x = tf32r(a.x); o0.y = tf32r(b.x); o0.z = tf32r(a.y); o0.w = tf32r(b.y);
        o1.x = tf32r(a.z); o1.y = tf32r(b.z); o1.z = tf32r(a.w); o1.w = tf32r(b.w);
        vd[2 * t] = o0; vd[2 * t + 1] = o1;
    }
}

// ---------------------------------------------------------------------------
// TF32 mma.sync GEMM:  C = A * W^T + bias.
// CTA tile 128x256x32, 256 threads (8 warps, warp tile 64x64), double-
// buffered smem, 1 CTA/SM.
// CMODE 0: out-proj (A=g_ctx via cp.async, W=g_owr, C=param)
// CMODE 1: q-proj   (A = RAW q, FUSED round+permute in loader: LDG stage kt+2
//                    held in regs, cvt+STS stage kt+1; W via cp.async;
//                    scatter g_qp tf32-rounded)
// CMODE 2: kv-proj  (z=0: g_kp; z=1: g_vpT transposed)
// ---------------------------------------------------------------------------
#define BKK 32
#define ROWPAD 40
#define A_STAGE (128 * ROWPAD)          // floats per A stage
#define B_STAGE (256 * ROWPAD)          // floats per B stage
static const int GEMM_SMEM = (2 * A_STAGE + 2 * B_STAGE) * 4;   // 122880 B

template <int CMODE>
__global__ void __launch_bounds__(256, 1)
tgemm_nt(const float* __restrict__ bias_ext, float* __restrict__ Cout,
         const float* __restrict__ Araw)
{
    extern __shared__ float sm[];
    float* smA = sm;                      // [2][128][40]
    float* smB = sm + 2 * A_STAGE;        // [2][256][40]

    const int tid  = threadIdx.x;
    const int lane = tid & 31;
    const int wid  = tid >> 5;            // 0..7
    const int wm   = wid & 1;             // warp row (2) -> 64 rows each
    const int wn   = wid >> 1;            // warp col (4) -> 64 cols each
    const int g    = lane >> 2;           // 0..7
    const int tig  = lane & 3;            // 0..3

    const int bm = blockIdx.y * 128;
    const int bn = blockIdx.x * 256;

    const float* A; const float* W; const float* bias;
    int z = 0;
    if (CMODE == 0)      { A = g_ctx; W = g_owr; bias = bias_ext; }
    else if (CMODE == 1) { A = nullptr; W = g_wr; bias = bias_ext; }
    else {
        z = blockIdx.z;
        A = z ? g_vg : g_kg;
        W = g_wr + (size_t)(z + 1) * DM * DM;
        bias = bias_ext + (size_t)(z + 1) * DM;
    }

    // --- W loader geometry (all modes): 8 float4/thread per stage ---
    const int lrow = tid >> 3;            // 0..31 (row within 32-row slab)
    const int lc4  = (tid & 7) * 4;       // 0..28 (k offset)
    const float* wptr[8];
#pragma unroll
    for (int j = 0; j < 8; j++)
        wptr[j] = W + (size_t)(bn + j * 32 + lrow) * DM + lc4;
    const uint32_t sdstB = smem_u32(smB + lrow * ROWPAD + lc4);

    // --- A loader: cp.async path (CMODE != 1) ---
    const float* aptr[4];
    uint32_t sdstA = 0;
    if (CMODE != 1) {
#pragma unroll
        for (int j = 0; j < 4; j++)
            aptr[j] = A + (size_t)(bm + j * 32 + lrow) * DM + lc4;
        sdstA = smem_u32(smA + lrow * ROWPAD + lc4);
    }

    // --- A loader: fused raw-q path (CMODE == 1) ---
    // thread covers row (tid>>1), 16 raw floats at k-offset (tid&1)*16.
    const int frow = tid >> 1;            // 0..127
    const int fk   = (tid & 1) * 16;      // 0 or 16
    const float4* qsrc = (CMODE == 1)
        ? (const float4*)(Araw + (size_t)(bm + frow) * DM + fk) : nullptr;
    float* fdstA = smA + frow * ROWPAD + fk;
    float raw[16];

#define LDG_A(ld) do {                                                        \
        const float4* _p = qsrc + (size_t)(ld) * (BKK / 4);                   \
        float4 _r0 = __ldg(_p);     float4 _r1 = __ldg(_p + 1);               \
        float4 _r2 = __ldg(_p + 2); float4 _r3 = __ldg(_p + 3);               \
        raw[0]=_r0.x;  raw[1]=_r0.y;  raw[2]=_r0.z;  raw[3]=_r0.w;            \
        raw[4]=_r1.x;  raw[5]=_r1.y;  raw[6]=_r1.z;  raw[7]=_r1.w;            \
        raw[8]=_r2.x;  raw[9]=_r2.y;  raw[10]=_r2.z; raw[11]=_r2.w;           \
        raw[12]=_r3.x; raw[13]=_r3.y; raw[14]=_r3.z; raw[15]=_r3.w;           \
    } while (0)

#define STS_A(ld) do {                                                        \
        float* _d = fdstA + ((ld) & 1) * A_STAGE;                             \
        float4 _o;                                                            \
        _o.x=tf32r(raw[0]);  _o.y=tf32r(raw[4]);  _o.z=tf32r(raw[1]);  _o.w=tf32r(raw[5]);  *(float4*)(_d)      = _o; \
        _o.x=tf32r(raw[2]);  _o.y=tf32r(raw[6]);  _o.z=tf32r(raw[3]);  _o.w=tf32r(raw[7]);  *(float4*)(_d + 4)  = _o; \
        _o.x=tf32r(raw[8]);  _o.y=tf32r(raw[12]); _o.z=tf32r(raw[9]);  _o.w=tf32r(raw[13]); *(float4*)(_d + 8)  = _o; \
        _o.x=tf32r(raw[10]); _o.y=tf32r(raw[14]); _o.z=tf32r(raw[11]); _o.w=tf32r(raw[15]); *(float4*)(_d + 12) = _o; \
    } while (0)

    float4 acc[4][8];
#pragma unroll
    for (int i = 0; i < 4; i++)
#pragma unroll
        for (int j = 0; j < 8; j++) acc[i][j] = make_float4(0.f, 0.f, 0.f, 0.f);

    const int nk = DM / BKK;              // 32

    // ---- prologue: stage 0 (+ raw LDG for stage 1 on fused path) ----
    if (CMODE == 1) {
        LDG_A(0);
        STS_A(0);
    } else {
#pragma unroll
        for (int j = 0; j < 4; j++)
            asm volatile("cp.async.cg.shared.global [%0], [%1], 16;\n"
                         :: "r"(sdstA + (uint32_t)(j * 32 * ROWPAD * 4)), "l"(aptr[j]));
    }
#pragma unroll
    for (int j = 0; j < 8; j++)
        asm volatile("cp.async.cg.shared.global [%0], [%1], 16;\n"
                     :: "r"(sdstB + (uint32_t)(j * 32 * ROWPAD * 4)), "l"(wptr[j]));
    asm volatile("cp.async.commit_group;\n");
    if (CMODE == 1) LDG_A(1);

    for (int kt = 0; kt < nk; kt++) {
        if (kt + 1 < nk) {
            uint32_t boB = (uint32_t)(((kt + 1) & 1) * B_STAGE * 4);
            int gofs = (kt + 1) * BKK;
            if (CMODE == 1) {
                STS_A(kt + 1);                       // from regs loaded last iter
            } else {
                uint32_t boA = (uint32_t)(((kt + 1) & 1) * A_STAGE * 4);
#pragma unroll
                for (int j = 0; j < 4; j++)
                    asm volatile("cp.async.cg.shared.global [%0], [%1], 16;\n"
                                 :: "r"(sdstA + boA + (uint32_t)(j * 32 * ROWPAD * 4)),
                                    "l"(aptr[j] + gofs));
            }
#pragma unroll
            for (int j = 0; j < 8; j++)
                asm volatile("cp.async.cg.shared.global [%0], [%1], 16;\n"
                             :: "r"(sdstB + boB + (uint32_t)(j * 32 * ROWPAD * 4)),
                                "l"(wptr[j] + gofs));
            asm volatile("cp.async.commit_group;\n");
            if (CMODE == 1 && kt + 2 < nk) LDG_A(kt + 2);
            asm volatile("cp.async.wait_group 1;\n" ::: "memory");
        } else {
            asm volatile("cp.async.wait_group 0;\n" ::: "memory");
        }
        __syncthreads();

        const float* Ab = smA + (kt & 1) * A_STAGE;
        const float* Bb = smB + (kt & 1) * B_STAGE;

#pragma unroll
        for (int ks = 0; ks < 4; ks++) {
            const int k0 = ks * 8 + 2 * tig;       // permuted layout: pair adjacent
            uint32_t afr[4][4];
            uint32_t bfr[8][2];
#pragma unroll
            for (int mt = 0; mt < 4; mt++) {
                int r = wm * 64 + mt * 16 + g;
                float2 a0 = *(const float2*)&Ab[r * ROWPAD + k0];
                float2 a1 = *(const float2*)&Ab[(r + 8) * ROWPAD + k0];
                afr[mt][0] = __float_as_uint(a0.x);
                afr[mt][1] = __float_as_uint(a1.x);
                afr[mt][2] = __float_as_uint(a0.y);
                afr[mt][3] = __float_as_uint(a1.y);
            }
#pragma unroll
            for (int nt = 0; nt < 8; nt++) {
                int n = wn * 64 + nt * 8 + g;
                float2 bb = *(const float2*)&Bb[n * ROWPAD + k0];
                bfr[nt][0] = __float_as_uint(bb.x);
                bfr[nt][1] = __float_as_uint(bb.y);
            }
#pragma unroll
            for (int mt = 0; mt < 4; mt++)
#pragma unroll
                for (int nt = 0; nt < 8; nt++)
                    mma_tf32(acc[mt][nt], afr[mt], bfr[nt]);
        }
        __syncthreads();
    }

#undef LDG_A
#undef STS_A

    // --- epilogue ---
#pragma unroll
    for (int nt = 0; nt < 8; nt++) {
        int col = bn + wn * 64 + nt * 8 + tig * 2;
        float b0 = bias[col], b1 = bias[col + 1];
#pragma unroll
        for (int mt = 0; mt < 4; mt++) {
            int row = bm + wm * 64 + mt * 16 + g;
            float2 v0 = make_float2(acc[mt][nt].x + b0, acc[mt][nt].y + b1);
            float2 v1 = make_float2(acc[mt][nt].z + b0, acc[mt][nt].w + b1);
            if (CMODE == 0) {
                *(float2*)(Cout + (size_t)row * DM + col) = v0;
                *(float2*)(Cout + (size_t)(row + 8) * DM + col) = v1;
            } else if (CMODE == 1) {
                int h_ = col >> 6, d_ = col & 63;
                int i0 = row >> 3, b_ = row & 7;
                v0.x = tf32r(v0.x); v0.y = tf32r(v0.y);
                v1.x = tf32r(v1.x); v1.y = tf32r(v1.y);
                *(float2*)(g_qp + (((size_t)(b_ * NH + h_)) * LQ + i0) * DH + d_) = v0;
                int i1 = (row + 8) >> 3;   // b_ unchanged (+8 rows = +1 i)
                *(float2*)(g_qp + (((size_t)(b_ * NH + h_)) * LQ + i1) * DH + d_) = v1;
            } else {
                int h_ = col >> 6, d_ = col & 63;
                int s0 = row >> 3, b_ = row & 7;
                int s1 = (row + 8) >> 3;
                if (z == 0) {
                    v0.x = tf32r(v0.x); v0.y = tf32r(v0.y);
                    v1.x = tf32r(v1.x); v1.y = tf32r(v1.y);
                    *(float2*)(g_kp + ((b_ * NH + h_) * NS + s0) * DH + d_) = v0;
                    *(float2*)(g_kp + ((b_ * NH + h_) * NS + s1) * DH + d_) = v1;
                } else {
                    // V transposed: [b][h][d][s]
                    float* base = g_vpT + (size_t)(b_ * NH + h_) * DH * NS;
                    base[(d_    ) * NS + s0] = tf32r(v0.x);
                    base[(d_ + 1) * NS + s0] = tf32r(v0.y);
                    base[(d_    ) * NS + s1] = tf32r(v1.x);
                    base[(d_ + 1) * NS + s1] = tf32r(v1.y);
                }
            }
        }
    }
}

// ---------------------------------------------------------------------------
// Tensor-core attention (unchanged from R14; g_ctx stored at k-PERMUTED cols).
// ---------------------------------------------------------------------------
#define SKPAD 68
#define SPPAD 132
#define ATT_SK   0
#define ATT_VT   (128 * SKPAD)                       // 8704
#define ATT_P    (ATT_VT + DH * SPPAD)               // 17152
#define ATT_SI   (ATT_P + 128 * SPPAD)               // 34048 (ints)
static const int ATTN_SMEM = (ATT_SI + NS) * 4;      // 136704 B

__global__ void __launch_bounds__(256)
attn_kernel()
{
    extern __shared__ float smf[];
    float* sK  = smf + ATT_SK;        // [128][68]   K tile  (s-major, dh cols)
    float* sVT = smf + ATT_VT;        // [64][132]   V^T tile (d rows, s cols)
    float* sP  = smf + ATT_P;         // [128][132]  P tile
    int*   sSI = (int*)(smf + ATT_SI);

    const int tid  = threadIdx.x;
    const int lane = tid & 31;
    const int wid  = tid >> 5;        // 0..7
    const int wr   = wid * 16;        // warp row band
    const int g    = lane >> 2;       // 0..7
    const int tig  = lane & 3;        // 0..3

    const int bh = blockIdx.y;
    const int b  = bh >> 4;
    const int h  = bh & 15;
    const int qbase = blockIdx.x * 128;

    if (tid < NS) sSI[tid] = g_sidx[tid];

    // ---- load K (128x64) and V^T (64x128) tiles ----
    {
        const float4* kp4 = (const float4*)(g_kp + (size_t)bh * NS * DH);
#pragma unroll
        for (int i = 0; i < 8; i++) {
            int x = tid + i * 256;                 // 0..2047
            int r = x >> 4, c4 = x & 15;
            *(float4*)(sK + r * SKPAD + c4 * 4) = kp4[x];
        }
        const float4* vt4 = (const float4*)(g_vpT + (size_t)bh * DH * NS);
#pragma unroll
        for (int i = 0; i < 8; i++) {
            int x = tid + i * 256;                 // 0..2047
            int r = x >> 5, c4 = x & 31;
            *(float4*)(sVT + r * SPPAD + c4 * 4) = vt4[x];
        }
    }

    // ---- Q fragments straight to registers (rows r0=wr+g, r1=r0+8) ----
    const int ia0 = qbase + wr + g;
    const int ia1 = ia0 + 8;
    float qa0[16], qa1[16];
    {
        const float* q0 = g_qp + ((size_t)bh * LQ + ia0) * DH;
        const float* q1 = g_qp + ((size_t)bh * LQ + ia1) * DH;
#pragma unroll
        for (int j = 0; j < 16; j++) {
            qa0[j] = __ldg(q0 + tig + 4 * j);
            qa1[j] = __ldg(q1 + tig + 4 * j);
        }
    }
    __syncthreads();

    // ---- scores: 16 n-tiles x 8 k-steps of m16n8k8 ----
    float4 acc[16];
#pragma unroll
    for (int nt = 0; nt < 16; nt++) acc[nt] = make_float4(0.f, 0.f, 0.f, 0.f);

#pragma unroll
    for (int kt = 0; kt < 8; kt++) {
        const int k0 = kt * 8 + tig;
        uint32_t afr[4];
        afr[0] = __float_as_uint(qa0[2 * kt]);
        afr[1] = __float_as_uint(qa1[2 * kt]);
        afr[2] = __float_as_uint(qa0[2 * kt + 1]);
        afr[3] = __float_as_uint(qa1[2 * kt + 1]);
#pragma unroll
        for (int nt = 0; nt < 16; nt++) {
            uint32_t bfr[2];
            const int n = nt * 8 + g;
            bfr[0] = __float_as_uint(sK[n * SKPAD + k0]);
            bfr[1] = __float_as_uint(sK[n * SKPAD + k0 + 4]);
            mma_tf32(acc[nt], afr, bfr);
        }
    }

    // ---- masked softmax in fragments ----
    int nvlo, nvhi;
    const int mkl = g_mkl[b];
    {
        int lo = 0, hi = NS;
        while (lo < hi) { int mid = (lo + hi) >> 1; if (sSI[mid] <= ia0) lo = mid + 1; else hi = mid; }
        nvlo = min(mkl, lo);
        lo = 0; hi = NS;
        while (lo < hi) { int mid = (lo + hi) >> 1; if (sSI[mid] <= ia1) lo = mid + 1; else hi = mid; }
        nvhi = min(mkl, lo);
    }

    float m0 = -1e30f, m1 = -1e30f;
#pragma unroll
    for (int nt = 0; nt < 16; nt++) {
        int c0 = nt * 8 + 2 * tig, c1 = c0 + 1;
        acc[nt].x *= 0.125f; acc[nt].y *= 0.125f;
        acc[nt].z *= 0.125f; acc[nt].w *= 0.125f;
        if (c0 < nvlo) m0 = fmaxf(m0, acc[nt].x);
        if (c1 < nvlo) m0 = fmaxf(m0, acc[nt].y);
        if (c0 < nvhi) m1 = fmaxf(m1, acc[nt].z);
        if (c1 < nvhi) m1 = fmaxf(m1, acc[nt].w);
    }
    m0 = fmaxf(m0, __shfl_xor_sync(0xffffffff, m0, 1));
    m0 = fmaxf(m0, __shfl_xor_sync(0xffffffff, m0, 2));
    m1 = fmaxf(m1, __shfl_xor_sync(0xffffffff, m1, 1));
    m1 = fmaxf(m1, __shfl_xor_sync(0xffffffff, m1, 2));

    float s0 = 0.f, s1 = 0.f;
    float* p0row = sP + (wr + g) * SPPAD;
    float* p1row = sP + (wr + g + 8) * SPPAD;
#pragma unroll
    for (int nt = 0; nt < 16; nt++) {
        int c0 = nt * 8 + 2 * tig;
        float px = (c0     < nvlo) ? __expf(acc[nt].x - m0) : 0.f;
        float py = (c0 + 1 < nvlo) ? __expf(acc[nt].y - m0) : 0.f;
        float pz = (c0     < nvhi) ? __expf(acc[nt].z - m1) : 0.f;
        float pw = (c0 + 1 < nvhi) ? __expf(acc[nt].w - m1) : 0.f;
        s0 += px + py;
        s1 += pz + pw;
        *(float2*)(p0row + c0) = make_float2(tf32r(px), tf32r(py));
        *(float2*)(p1row + c0) = make_float2(tf32r(pz), tf32r(pw));
    }
    s0 += __shfl_xor_sync(0xffffffff, s0, 1);
    s0 += __shfl_xor_sync(0xffffffff, s0, 2);
    s1 += __shfl_xor_sync(0xffffffff, s1, 1);
    s1 += __shfl_xor_sync(0xffffffff, s1, 2);
    const float inv0 = 1.0f / s0;
    const float inv1 = 1.0f / s1;
    __syncwarp();    // sP band is warp-local: warp-visible is enough

    // ---- ctx = P (16x128) @ V^T : 8 n-tiles x 16 k-steps ----
    float4 cacc[8];
#pragma unroll
    for (int nt = 0; nt < 8; nt++) cacc[nt] = make_float4(0.f, 0.f, 0.f, 0.f);

#pragma unroll
    for (int kt = 0; kt < 16; kt++) {
        const int k0 = kt * 8 + tig;
        uint32_t afr[4];
        afr[0] = __float_as_uint(p0row[k0]);
        afr[1] = __float_as_uint(p1row[k0]);
        afr[2] = __float_as_uint(p0row[k0 + 4]);
        afr[3] = __float_as_uint(p1row[k0 + 4]);
#pragma unroll
        for (int nt = 0; nt < 8; nt++) {
            uint32_t bfr[2];
            const int n = nt * 8 + g;
            bfr[0] = __float_as_uint(sVT[n * SPPAD + k0]);
            bfr[1] = __float_as_uint(sVT[n * SPPAD + k0 + 4]);
            mma_tf32(cacc[nt], afr, bfr);
        }
    }

    // ---- epilogue: scale, round to tf32, store to g_ctx at PERMUTED cols ----
    const int p0 = kperm(2 * tig);
    const int p1 = kperm(2 * tig + 1);
#pragma unroll
    for (int nt = 0; nt < 8; nt++) {
        float* base0 = g_ctx + ((size_t)ia0 * BB + b) * DM + h * DH + nt * 8;
        float* base1 = g_ctx + ((size_t)ia1 * BB + b) * DM + h * DH + nt * 8;
        base0[p0] = tf32r(cacc[nt].x * inv0);
        base0[p1] = tf32r(cacc[nt].y * inv0);
        base1[p0] = tf32r(cacc[nt].z * inv1);
        base1[p1] = tf32r(cacc[nt].w * inv1);
    }
}

extern "C" void kernel_launch(void* const* d_in, const int* in_sizes, int n_in,
                              void* d_out, int out_size)
{
    const float* q    = (const float*)d_in[0];
    const float* k    = (const float*)d_in[1];
    const float* v    = (const float*)d_in[2];
    const void*  klen = d_in[3];
    const void*  sidx = d_in[4];
    const float* ipw  = (const float*)d_in[5];   // [3D, D]
    const float* ipb  = (const float*)d_in[6];   // [3D]
    const float* ow   = (const float*)d_in[7];   // [D, D]
    const float* ob   = (const float*)d_in[8];   // [D]
    float* out = (float*)d_out;

    (void)in_sizes; (void)n_in; (void)out_size;

    cudaFuncSetAttribute(attn_kernel, cudaFuncAttributeMaxDynamicSharedMemorySize, ATTN_SMEM);
    cudaFuncSetAttribute(tgemm_nt<0>, cudaFuncAttributeMaxDynamicSharedMemorySize, GEMM_SMEM);
    cudaFuncSetAttribute(tgemm_nt<1>, cudaFuncAttributeMaxDynamicSharedMemorySize, GEMM_SMEM);
    cudaFuncSetAttribute(tgemm_nt<2>, cudaFuncAttributeMaxDynamicSharedMemorySize, GEMM_SMEM);

    setup_kernel<<<1, 128>>>(sidx, klen);

    // pre-round (tf32) + k-permute weights and gathered k/v (q handled in-GEMM)
    gather_round_kernel<<<NS * BB, 128>>>(k, v);
    round_perm_kernel<<<512, 256>>>((const float4*)ipw, (3 * DM * DM) / 8, 1);
    round_perm_kernel<<<512, 256>>>((const float4*)ow,  (DM * DM) / 8,     2);

    // k/v projections (merged, z selects k vs v): M = S*B = 1024
    tgemm_nt<2><<<dim3(DM / 256, (NS * BB) / 128, 2), 256, GEMM_SMEM>>>(ipb, nullptr, nullptr);
    // q projection: M = L*B = 32768, A-loader fuses round+permute from raw q
    tgemm_nt<1><<<dim3(DM / 256, (LQ * BB) / 128), 256, GEMM_SMEM>>>(ipb, nullptr, q);
    // fused masked attention (tensor-core)
    attn_kernel<<<dim3(LQ / 128, BB * NH), 256, ATTN_SMEM>>>();
    // output projection
    tgemm_nt<0><<<dim3(DM / 256, (LQ * BB) / 128), 256, GEMM_SMEM>>>(ob, out, nullptr);
}

// round 17
// speedup vs baseline: 1.0416x; 1.0416x over previous
#include <cuda_runtime.h>
#include <cstdint>

#define LQ 4096
#define BB 8
#define DM 1024
#define NH 16
#define DH 64
#define NS 128

// ---------------------------------------------------------------------------
// Scratch (static device globals — allocation-free per harness rules)
// k-dim of all GEMM operands is stored PERMUTED within 8-blocks:
//   pos(k) = (k & ~7) | ((k&3)<<1) | ((k&4)>>2)
// so that mma's per-thread k-pair (k, k+4) is memory-adjacent (LDS.64 frags).
// ---------------------------------------------------------------------------
__device__ float g_qp[(size_t)BB * NH * LQ * DH];   // [b][h][i][dh]   (tf32, unpermuted)
__device__ float g_kp[BB * NH * NS * DH];           // [b][h][s][dh]   (tf32, unpermuted)
__device__ float g_vpT[BB * NH * DH * NS];          // [b][h][d][s]    (tf32, unpermuted)
__device__ float g_ctx[(size_t)LQ * BB * DM];       // [i*B+b][D]      (tf32, k-PERMUTED)
__device__ float g_qr[(size_t)LQ * BB * DM];        // tf32 q          (k-PERMUTED)
__device__ float g_kg[NS * BB * DM];                // gathered k rows (k-PERMUTED)
__device__ float g_vg[NS * BB * DM];                // gathered v rows (k-PERMUTED)
__device__ float g_wr[3 * DM * DM];                 // in_proj_weight  (k-PERMUTED)
__device__ float g_owr[DM * DM];                    // out_w           (k-PERMUTED)
__device__ int   g_sidx[NS];
__device__ int   g_mkl[BB];

__device__ __forceinline__ uint32_t smem_u32(const void* p) {
    return (uint32_t)__cvta_generic_to_shared(p);
}
__device__ __forceinline__ float tf32r(float x) {   // round-to-nearest tf32
    uint32_t u;
    asm volatile("cvt.rna.tf32.f32 %0, %1;\n" : "=r"(u) : "f"(x));
    return __uint_as_float(u);
}
__device__ __forceinline__ int kperm(int k) {       // within-8 interleave
    return (k & ~7) | ((k & 3) << 1) | ((k & 4) >> 2);
}
__device__ __forceinline__ void mma_tf32(float4& d, const uint32_t a[4], const uint32_t b[2]) {
    asm volatile(
        "mma.sync.aligned.m16n8k8.row.col.f32.tf32.tf32.f32 "
        "{%0,%1,%2,%3}, {%4,%5,%6,%7}, {%8,%9}, {%0,%1,%2,%3};\n"
        : "+f"(d.x), "+f"(d.y), "+f"(d.z), "+f"(d.w)
        : "r"(a[0]), "r"(a[1]), "r"(a[2]), "r"(a[3]), "r"(b[0]), "r"(b[1]));
}

// ---------------------------------------------------------------------------
// Setup: normalize sampled_index / key_length (int32 or int64 on the wire).
// ---------------------------------------------------------------------------
__global__ void setup_kernel(const void* sidx_raw, const void* klen_raw)
{
    __shared__ int s_sidx[NS];
    __shared__ int s_klen[BB];
    int t = threadIdx.x;  // 128 threads

    const int* si = (const int*)sidx_raw;
    int sv;
    if (si[1] == 0) sv = (int)((const long long*)sidx_raw)[t];
    else            sv = si[t];
    s_sidx[t] = sv;
    g_sidx[t] = sv;

    if (t < BB) {
        const int* ki = (const int*)klen_raw;
        int kv;
        if (ki[1] == 0) kv = (int)((const long long*)klen_raw)[t];
        else            kv = ki[t];
        s_klen[t] = kv;
    }
    __syncthreads();
    if (t < BB) {
        int c = 0;
        for (int s = 0; s < NS; s++) c += (s_sidx[s] < s_klen[t]) ? 1 : 0;
        g_mkl[t] = c;
    }
}

// ---------------------------------------------------------------------------
// Pre-round fp32 -> tf32 AND apply the within-8 k-permutation.
// sel: 0=g_qr 1=g_wr 2=g_owr
// ---------------------------------------------------------------------------
__global__ void round_perm_kernel(const float4* __restrict__ src, int n8, int sel)
{
    float4* dst = sel == 0 ? (float4*)g_qr : sel == 1 ? (float4*)g_wr : (float4*)g_owr;
    for (int i = blockIdx.x * blockDim.x + threadIdx.x; i < n8; i += gridDim.x * blockDim.x) {
        float4 a = src[2 * i];
        float4 b = src[2 * i + 1];
        float4 o0, o1;
        o0.x = tf32r(a.x); o0.y = tf32r(b.x); o0.z = tf32r(a.y); o0.w = tf32r(b.y);
        o1.x = tf32r(a.z); o1.y = tf32r(b.z); o1.z = tf32r(a.w); o1.w = tf32r(b.w);
        dst[2 * i] = o0;
        dst[2 * i + 1] = o1;
    }
}

// Gather sampled k/v rows, round + permute: row = s*BB+b -> src row sidx[s]*BB+b
__global__ void gather_round_kernel(const float* __restrict__ k, const float* __restrict__ v)
{
    int row = blockIdx.x;                      // 0..1023
    int src = g_sidx[row >> 3] * BB + (row & 7);
    const float4* ks = (const float4*)(k + (size_t)src * DM);
    const float4* vs = (const float4*)(v + (size_t)src * DM);
    float4* kd = (float4*)(g_kg + (size_t)row * DM);
    float4* vd = (float4*)(g_vg + (size_t)row * DM);
    int t = threadIdx.x;                       // 128 threads, DM/8 = 128 blocks
    {
        float4 a = ks[2 * t], b = ks[2 * t + 1];
        float4 o0, o1;
        o0.x = tf32r(a.x); o0.y = tf32r(b.x); o0.z = tf32r(a.y); o0.w = tf32r(b.y);
        o1.x = tf32r(a.z); o1.y = tf32r(b.z); o1.z = tf32r(a.w); o1.w = tf32r(b.w);
        kd[2 * t] = o0; kd[2 * t + 1] = o1;
    }
    {
        float4 a = vs[2 * t], b = vs[2 * t + 1];
        float4 o0, o1;
        o0.x = tf32r(a.x); o0.y = tf32r(b.x); o0.z = tf32r(a.y); o0.w = tf32r(b.y);
        o1.x = tf32r(a.z); o1.y = tf32r(b.z); o1.z = tf32r(a.w); o1.w = tf32r(b.w);
        vd[2 * t] = o0; vd[2 * t + 1] = o1;
    }
}

// ---------------------------------------------------------------------------
// TF32 mma.sync GEMM:  C = A * W^T + bias.  Inputs pre-rounded AND k-permuted.
// CTA tile 128x256x32, 256 threads (8 warps, warp tile 64x64), double-
// buffered cp.async smem, 1 CTA/SM.  (R14 proven config)
// CMODE: 0 = out-proj (A=g_ctx, W=g_owr, C=param, raw fp32 out)
//        1 = q-proj   (A=g_qr, scatter g_qp, tf32-rounded)
//        2 = kv-proj  (z=0: g_kp rounded; z=1: g_vpT transposed+rounded)
// ---------------------------------------------------------------------------
#define BKK 32
#define ROWPAD 40
#define A_STAGE (128 * ROWPAD)          // floats per A stage
#define B_STAGE (256 * ROWPAD)          // floats per B stage
static const int GEMM_SMEM = (2 * A_STAGE + 2 * B_STAGE) * 4;   // 122880 B

template <int CMODE>
__global__ void __launch_bounds__(256, 1)
tgemm_nt(const float* __restrict__ bias_ext, float* __restrict__ Cout)
{
    extern __shared__ float sm[];
    float* smA = sm;                      // [2][128][40]
    float* smB = sm + 2 * A_STAGE;        // [2][256][40]

    const int tid  = threadIdx.x;
    const int lane = tid & 31;
    const int wid  = tid >> 5;            // 0..7
    const int wm   = wid & 1;             // warp row (2) -> 64 rows each
    const int wn   = wid >> 1;            // warp col (4) -> 64 cols each
    const int g    = lane >> 2;           // 0..7
    const int tig  = lane & 3;            // 0..3

    const int bm = blockIdx.y * 128;
    const int bn = blockIdx.x * 256;

    const float* A; const float* W; const float* bias;
    int z = 0;
    if (CMODE == 0)      { A = g_ctx; W = g_owr; bias = bias_ext; }
    else if (CMODE == 1) { A = g_qr;  W = g_wr;  bias = bias_ext; }
    else {
        z = blockIdx.z;
        A = z ? g_vg : g_kg;
        W = g_wr + (size_t)(z + 1) * DM * DM;
        bias = bias_ext + (size_t)(z + 1) * DM;
    }

    // --- loader geometry: 256 threads; A: 4 float4/thread, B: 8 float4/thread ---
    const int lrow = tid >> 3;            // 0..31 (row within 32-row slab)
    const int lc4  = (tid & 7) * 4;       // 0..28 (k offset)

    const float* aptr[4];
    const float* wptr[8];
#pragma unroll
    for (int j = 0; j < 4; j++)
        aptr[j] = A + (size_t)(bm + j * 32 + lrow) * DM + lc4;
#pragma unroll
    for (int j = 0; j < 8; j++)
        wptr[j] = W + (size_t)(bn + j * 32 + lrow) * DM + lc4;

    const uint32_t sdstA = smem_u32(smA + lrow * ROWPAD + lc4);
    const uint32_t sdstB = smem_u32(smB + lrow * ROWPAD + lc4);

    float4 acc[4][8];
#pragma unroll
    for (int i = 0; i < 4; i++)
#pragma unroll
        for (int j = 0; j < 8; j++) acc[i][j] = make_float4(0.f, 0.f, 0.f, 0.f);

    const int nk = DM / BKK;              // 32

    // prologue: stage 0
#pragma unroll
    for (int j = 0; j < 4; j++)
        asm volatile("cp.async.cg.shared.global [%0], [%1], 16;\n"
                     :: "r"(sdstA + (uint32_t)(j * 32 * ROWPAD * 4)), "l"(aptr[j]));
#pragma unroll
    for (int j = 0; j < 8; j++)
        asm volatile("cp.async.cg.shared.global [%0], [%1], 16;\n"
                     :: "r"(sdstB + (uint32_t)(j * 32 * ROWPAD * 4)), "l"(wptr[j]));
    asm volatile("cp.async.commit_group;\n");

    for (int kt = 0; kt < nk; kt++) {
        if (kt + 1 < nk) {
            uint32_t boA = (uint32_t)(((kt + 1) & 1) * A_STAGE * 4);
            uint32_t boB = (uint32_t)(((kt + 1) & 1) * B_STAGE * 4);
            int gofs = (kt + 1) * BKK;
#pragma unroll
            for (int j = 0; j < 4; j++)
                asm volatile("cp.async.cg.shared.global [%0], [%1], 16;\n"
                             :: "r"(sdstA + boA + (uint32_t)(j * 32 * ROWPAD * 4)),
                                "l"(aptr[j] + gofs));
#pragma unroll
            for (int j = 0; j < 8; j++)
                asm volatile("cp.async.cg.shared.global [%0], [%1], 16;\n"
                             :: "r"(sdstB + boB + (uint32_t)(j * 32 * ROWPAD * 4)),
                                "l"(wptr[j] + gofs));
            asm volatile("cp.async.commit_group;\n");
            asm volatile("cp.async.wait_group 1;\n" ::: "memory");
        } else {
            asm volatile("cp.async.wait_group 0;\n" ::: "memory");
        }
        __syncthreads();

        const float* Ab = smA + (kt & 1) * A_STAGE;
        const float* Bb = smB + (kt & 1) * B_STAGE;

#pragma unroll
        for (int ks = 0; ks < 4; ks++) {
            const int k0 = ks * 8 + 2 * tig;       // permuted layout: pair adjacent
            uint32_t afr[4][4];
            uint32_t bfr[8][2];
#pragma unroll
            for (int mt = 0; mt < 4; mt++) {
                int r = wm * 64 + mt * 16 + g;
                float2 a0 = *(const float2*)&Ab[r * ROWPAD + k0];
                float2 a1 = *(const float2*)&Ab[(r + 8) * ROWPAD + k0];
                afr[mt][0] = __float_as_uint(a0.x);
                afr[mt][1] = __float_as_uint(a1.x);
                afr[mt][2] = __float_as_uint(a0.y);
                afr[mt][3] = __float_as_uint(a1.y);
            }
#pragma unroll
            for (int nt = 0; nt < 8; nt++) {
                int n = wn * 64 + nt * 8 + g;
                float2 bb = *(const float2*)&Bb[n * ROWPAD + k0];
                bfr[nt][0] = __float_as_uint(bb.x);
                bfr[nt][1] = __float_as_uint(bb.y);
            }
#pragma unroll
            for (int mt = 0; mt < 4; mt++)
#pragma unroll
                for (int nt = 0; nt < 8; nt++)
                    mma_tf32(acc[mt][nt], afr[mt], bfr[nt]);
        }
        __syncthreads();
    }

    // --- epilogue ---
#pragma unroll
    for (int nt = 0; nt < 8; nt++) {
        int col = bn + wn * 64 + nt * 8 + tig * 2;
        float b0 = bias[col], b1 = bias[col + 1];
#pragma unroll
        for (int mt = 0; mt < 4; mt++) {
            int row = bm + wm * 64 + mt * 16 + g;
            float2 v0 = make_float2(acc[mt][nt].x + b0, acc[mt][nt].y + b1);
            float2 v1 = make_float2(acc[mt][nt].z + b0, acc[mt][nt].w + b1);
            if (CMODE == 0) {
                *(float2*)(Cout + (size_t)row * DM + col) = v0;
                *(float2*)(Cout + (size_t)(row + 8) * DM + col) = v1;
            } else if (CMODE == 1) {
                int h_ = col >> 6, d_ = col & 63;
                int i0 = row >> 3, b_ = row & 7;
                v0.x = tf32r(v0.x); v0.y = tf32r(v0.y);
                v1.x = tf32r(v1.x); v1.y = tf32r(v1.y);
                *(float2*)(g_qp + (((size_t)(b_ * NH + h_)) * LQ + i0) * DH + d_) = v0;
                int i1 = (row + 8) >> 3;   // b_ unchanged (+8 rows = +1 i)
                *(float2*)(g_qp + (((size_t)(b_ * NH + h_)) * LQ + i1) * DH + d_) = v1;
            } else {
                int h_ = col >> 6, d_ = col & 63;
                int s0 = row >> 3, b_ = row & 7;
                int s1 = (row + 8) >> 3;
                if (z == 0) {
                    v0.x = tf32r(v0.x); v0.y = tf32r(v0.y);
                    v1.x = tf32r(v1.x); v1.y = tf32r(v1.y);
                    *(float2*)(g_kp + ((b_ * NH + h_) * NS + s0) * DH + d_) = v0;
                    *(float2*)(g_kp + ((b_ * NH + h_) * NS + s1) * DH + d_) = v1;
                } else {
                    // V transposed: [b][h][d][s]
                    float* base = g_vpT + (size_t)(b_ * NH + h_) * DH * NS;
                    base[(d_    ) * NS + s0] = tf32r(v0.x);
                    base[(d_ + 1) * NS + s0] = tf32r(v0.y);
                    base[(d_    ) * NS + s1] = tf32r(v1.x);
                    base[(d_ + 1) * NS + s1] = tf32r(v1.y);
                }
            }
        }
    }
}

// ---------------------------------------------------------------------------
// Tensor-core attention with CAUSAL TILE PRUNING: block-uniform upper bound
// nvmax = min(mkl[b], #{sidx <= qbase+127}); statically-unrolled tile loops
// with uniform guards (nt*8 < nvmax) skip score/softmax/ctx work on tiles
// that are fully masked for the whole block.  Bit-identical output (skipped
// tiles contributed exact zeros before).
// ---------------------------------------------------------------------------
#define SKPAD 68
#define SPPAD 132
#define ATT_SK   0
#define ATT_VT   (128 * SKPAD)                       // 8704
#define ATT_P    (ATT_VT + DH * SPPAD)               // 17152
#define ATT_SI   (ATT_P + 128 * SPPAD)               // 34048 (ints)
static const int ATTN_SMEM = (ATT_SI + NS) * 4;      // 136704 B

__global__ void __launch_bounds__(256)
attn_kernel()
{
    extern __shared__ float smf[];
    float* sK  = smf + ATT_SK;        // [128][68]   K tile  (s-major, dh cols)
    float* sVT = smf + ATT_VT;        // [64][132]   V^T tile (d rows, s cols)
    float* sP  = smf + ATT_P;         // [128][132]  P tile
    int*   sSI = (int*)(smf + ATT_SI);

    const int tid  = threadIdx.x;
    const int lane = tid & 31;
    const int wid  = tid >> 5;        // 0..7
    const int wr   = wid * 16;        // warp row band
    const int g    = lane >> 2;       // 0..7
    const int tig  = lane & 3;        // 0..3

    const int bh = blockIdx.y;
    const int b  = bh >> 4;
    const int h  = bh & 15;
    const int qbase = blockIdx.x * 128;

    if (tid < NS) sSI[tid] = g_sidx[tid];

    // ---- load K (128x64) and V^T (64x128) tiles ----
    {
        const float4* kp4 = (const float4*)(g_kp + (size_t)bh * NS * DH);
#pragma unroll
        for (int i = 0; i < 8; i++) {
            int x = tid + i * 256;                 // 0..2047
            int r = x >> 4, c4 = x & 15;
            *(float4*)(sK + r * SKPAD + c4 * 4) = kp4[x];
        }
        const float4* vt4 = (const float4*)(g_vpT + (size_t)bh * DH * NS);
#pragma unroll
        for (int i = 0; i < 8; i++) {
            int x = tid + i * 256;                 // 0..2047
            int r = x >> 5, c4 = x & 31;
            *(float4*)(sVT + r * SPPAD + c4 * 4) = vt4[x];
        }
    }

    // ---- Q fragments straight to registers (rows r0=wr+g, r1=r0+8) ----
    const int ia0 = qbase + wr + g;
    const int ia1 = ia0 + 8;
    float qa0[16], qa1[16];
    {
        const float* q0 = g_qp + ((size_t)bh * LQ + ia0) * DH;
        const float* q1 = g_qp + ((size_t)bh * LQ + ia1) * DH;
#pragma unroll
        for (int j = 0; j < 16; j++) {
            qa0[j] = __ldg(q0 + tig + 4 * j);
            qa1[j] = __ldg(q1 + tig + 4 * j);
        }
    }
    __syncthreads();

    // ---- prefix bounds: per-row nv and block-uniform nvmax ----
    const int mkl = g_mkl[b];
    int nvlo, nvhi, nvmax;
    {
        int lo = 0, hi = NS;
        while (lo < hi) { int mid = (lo + hi) >> 1; if (sSI[mid] <= ia0) lo = mid + 1; else hi = mid; }
        nvlo = min(mkl, lo);
        lo = 0; hi = NS;
        while (lo < hi) { int mid = (lo + hi) >> 1; if (sSI[mid] <= ia1) lo = mid + 1; else hi = mid; }
        nvhi = min(mkl, lo);
        lo = 0; hi = NS;
        int qlast = qbase + 127;
        while (lo < hi) { int mid = (lo + hi) >> 1; if (sSI[mid] <= qlast) lo = mid + 1; else hi = mid; }
        nvmax = min(mkl, lo);                  // uniform across CTA
    }

    // ---- scores: nt-outer (A frags are register aliases), tiles pruned ----
    float4 acc[16];
#pragma unroll
    for (int nt = 0; nt < 16; nt++) acc[nt] = make_float4(0.f, 0.f, 0.f, 0.f);

#pragma unroll
    for (int nt = 0; nt < 16; nt++) {
        if (nt * 8 < nvmax) {
            const int n = nt * 8 + g;
#pragma unroll
            for (int kt = 0; kt < 8; kt++) {
                const int k0 = kt * 8 + tig;
                uint32_t afr[4];
                afr[0] = __float_as_uint(qa0[2 * kt]);
                afr[1] = __float_as_uint(qa1[2 * kt]);
                afr[2] = __float_as_uint(qa0[2 * kt + 1]);
                afr[3] = __float_as_uint(qa1[2 * kt + 1]);
                uint32_t bfr[2];
                bfr[0] = __float_as_uint(sK[n * SKPAD + k0]);
                bfr[1] = __float_as_uint(sK[n * SKPAD + k0 + 4]);
                mma_tf32(acc[nt], afr, bfr);
            }
        }
    }

    // ---- masked softmax in fragments (pruned tiles untouched) ----
    float m0 = -1e30f, m1 = -1e30f;
#pragma unroll
    for (int nt = 0; nt < 16; nt++) {
        if (nt * 8 < nvmax) {
            int c0 = nt * 8 + 2 * tig, c1 = c0 + 1;
            acc[nt].x *= 0.125f; acc[nt].y *= 0.125f;
            acc[nt].z *= 0.125f; acc[nt].w *= 0.125f;
            if (c0 < nvlo) m0 = fmaxf(m0, acc[nt].x);
            if (c1 < nvlo) m0 = fmaxf(m0, acc[nt].y);
            if (c0 < nvhi) m1 = fmaxf(m1, acc[nt].z);
            if (c1 < nvhi) m1 = fmaxf(m1, acc[nt].w);
        }
    }
    m0 = fmaxf(m0, __shfl_xor_sync(0xffffffff, m0, 1));
    m0 = fmaxf(m0, __shfl_xor_sync(0xffffffff, m0, 2));
    m1 = fmaxf(m1, __shfl_xor_sync(0xffffffff, m1, 1));
    m1 = fmaxf(m1, __shfl_xor_sync(0xffffffff, m1, 2));

    float s0 = 0.f, s1 = 0.f;
    float* p0row = sP + (wr + g) * SPPAD;
    float* p1row = sP + (wr + g + 8) * SPPAD;
#pragma unroll
    for (int nt = 0; nt < 16; nt++) {
        if (nt * 8 < nvmax) {
            int c0 = nt * 8 + 2 * tig;
            float px = (c0     < nvlo) ? __expf(acc[nt].x - m0) : 0.f;
            float py = (c0 + 1 < nvlo) ? __expf(acc[nt].y - m0) : 0.f;
            float pz = (c0     < nvhi) ? __expf(acc[nt].z - m1) : 0.f;
            float pw = (c0 + 1 < nvhi) ? __expf(acc[nt].w - m1) : 0.f;
            s0 += px + py;
            s1 += pz + pw;
            *(float2*)(p0row + c0) = make_float2(tf32r(px), tf32r(py));
            *(float2*)(p1row + c0) = make_float2(tf32r(pz), tf32r(pw));
        }
    }
    s0 += __shfl_xor_sync(0xffffffff, s0, 1);
    s0 += __shfl_xor_sync(0xffffffff, s0, 2);
    s1 += __shfl_xor_sync(0xffffffff, s1, 1);
    s1 += __shfl_xor_sync(0xffffffff, s1, 2);
    const float inv0 = 1.0f / s0;
    const float inv1 = 1.0f / s1;
    __syncwarp();    // sP band is warp-local: warp-visible is enough

    // ---- ctx = P (16x128) @ V^T : 8 n-tiles x pruned k-steps ----
    float4 cacc[8];
#pragma unroll
    for (int nt = 0; nt < 8; nt++) cacc[nt] = make_float4(0.f, 0.f, 0.f, 0.f);

#pragma unroll
    for (int kt = 0; kt < 16; kt++) {
        if (kt * 8 < nvmax) {
            const int k0 = kt * 8 + tig;
            uint32_t afr[4];
            afr[0] = __float_as_uint(p0row[k0]);
            afr[1] = __float_as_uint(p1row[k0]);
            afr[2] = __float_as_uint(p0row[k0 + 4]);
            afr[3] = __float_as_uint(p1row[k0 + 4]);
#pragma unroll
            for (int nt = 0; nt < 8; nt++) {
                uint32_t bfr[2];
                const int n = nt * 8 + g;
                bfr[0] = __float_as_uint(sVT[n * SPPAD + k0]);
                bfr[1] = __float_as_uint(sVT[n * SPPAD + k0 + 4]);
                mma_tf32(cacc[nt], afr, bfr);
            }
        }
    }

    // ---- epilogue: scale, round to tf32, store to g_ctx at PERMUTED cols ----
    const int p0 = kperm(2 * tig);
    const int p1 = kperm(2 * tig + 1);
#pragma unroll
    for (int nt = 0; nt < 8; nt++) {
        float* base0 = g_ctx + ((size_t)ia0 * BB + b) * DM + h * DH + nt * 8;
        float* base1 = g_ctx + ((size_t)ia1 * BB + b) * DM + h * DH + nt * 8;
        base0[p0] = tf32r(cacc[nt].x * inv0);
        base0[p1] = tf32r(cacc[nt].y * inv0);
        base1[p0] = tf32r(cacc[nt].z * inv1);
        base1[p1] = tf32r(cacc[nt].w * inv1);
    }
}

extern "C" void kernel_launch(void* const* d_in, const int* in_sizes, int n_in,
                              void* d_out, int out_size)
{
    const float* q    = (const float*)d_in[0];
    const float* k    = (const float*)d_in[1];
    const float* v    = (const float*)d_in[2];
    const void*  klen = d_in[3];
    const void*  sidx = d_in[4];
    const float* ipw  = (const float*)d_in[5];   // [3D, D]
    const float* ipb  = (const float*)d_in[6];   // [3D]
    const float* ow   = (const float*)d_in[7];   // [D, D]
    const float* ob   = (const float*)d_in[8];   // [D]
    float* out = (float*)d_out;

    (void)in_sizes; (void)n_in; (void)out_size;

    cudaFuncSetAttribute(attn_kernel, cudaFuncAttributeMaxDynamicSharedMemorySize, ATTN_SMEM);
    cudaFuncSetAttribute(tgemm_nt<0>, cudaFuncAttributeMaxDynamicSharedMemorySize, GEMM_SMEM);
    cudaFuncSetAttribute(tgemm_nt<1>, cudaFuncAttributeMaxDynamicSharedMemorySize, GEMM_SMEM);
    cudaFuncSetAttribute(tgemm_nt<2>, cudaFuncAttributeMaxDynamicSharedMemorySize, GEMM_SMEM);

    setup_kernel<<<1, 128>>>(sidx, klen);

    // pre-round (tf32) + k-permute inputs
    gather_round_kernel<<<NS * BB, 128>>>(k, v);
    round_perm_kernel<<<2048, 256>>>((const float4*)q,   (LQ * BB * DM) / 8, 0);
    round_perm_kernel<<<512, 256>>>((const float4*)ipw, (3 * DM * DM) / 8,  1);
    round_perm_kernel<<<512, 256>>>((const float4*)ow,  (DM * DM) / 8,      2);

    // k/v projections (merged, z selects k vs v): M = S*B = 1024
    tgemm_nt<2><<<dim3(DM / 256, (NS * BB) / 128, 2), 256, GEMM_SMEM>>>(ipb, nullptr);
    // q projection: M = L*B = 32768
    tgemm_nt<1><<<dim3(DM / 256, (LQ * BB) / 128), 256, GEMM_SMEM>>>(ipb, nullptr);
    // fused masked attention (tensor-core, causal tile pruning)
    attn_kernel<<<dim3(LQ / 128, BB * NH), 256, ATTN_SMEM>>>();
    // output projection
    tgemm_nt<0><<<dim3(DM / 256, (LQ * BB) / 128), 256, GEMM_SMEM>>>(ob, out);
}